// round 14
// baseline (speedup 1.0000x reference)
#include <cuda_runtime.h>
#include <cuda_fp16.h>

// V=100000, K=32, F=64.
// out[v, 0:64]   = mean over K neighbours of x[idxs[v,k], :]
// out[v, 64:128] = max  over K neighbours
//
// Two kernels + PDL. Gather = R11 layout (2 vertices/warp, half-warp per
// row, LDG.64 per lane -> 2 lines per request). R14 change: the two loads
// of each k-pair are fused into ONE asm volatile block so ptxas cannot
// re-serialize them (it collapsed the C++-level pipelines of R4/R13 back to
// 32 regs / MLP=1 every time). MLP=2 at occ ~75% raises outstanding loads
// per SMSP from ~14 to ~24, covering the ~7us of exposed L2 latency
// (L1-busy 20us vs wall 27.4us at issue 46%).

#define KNN  32
#define FDIM 64
#define VMAX 100000

__device__ __align__(16) __half2 g_xh[VMAX * (FDIM / 2)];   // 12.8 MB

__global__ __launch_bounds__(256)
void convert_kernel(const float4* __restrict__ x4, int n8)   // n8 = V*F/8
{
    int i = blockIdx.x * blockDim.x + threadIdx.x;
    if (i < n8) {
        float4 a = x4[2 * i];
        float4 b = x4[2 * i + 1];
        __half2 h0 = __floats2half2_rn(a.x, a.y);
        __half2 h1 = __floats2half2_rn(a.z, a.w);
        __half2 h2 = __floats2half2_rn(b.x, b.y);
        __half2 h3 = __floats2half2_rn(b.z, b.w);
        int4 packed;
        packed.x = *(const int*)&h0;
        packed.y = *(const int*)&h1;
        packed.z = *(const int*)&h2;
        packed.w = *(const int*)&h3;
        *reinterpret_cast<int4*>(&g_xh[4 * i]) = packed;
    }
    asm volatile("griddepcontrol.launch_dependents;" ::: "memory");
}

__device__ __forceinline__ void stg_cs_f4(float4* p, float4 v)
{
    asm volatile("st.global.cs.v4.f32 [%0], {%1,%2,%3,%4};"
                 :: "l"(p), "f"(v.x), "f"(v.y), "f"(v.z), "f"(v.w)
                 : "memory");
}

__global__ __launch_bounds__(256, 7)   // 36-reg budget
void knn_mean_max_kernel(const int2* __restrict__ idx2,
                         float4*     __restrict__ out4,
                         int V)
{
    const int warp = (blockIdx.x * blockDim.x + threadIdx.x) >> 5;
    const int lane = threadIdx.x & 31;
    const int h    = lane >> 4;        // which vertex of the pair
    const int hl   = lane & 15;        // position within half-warp
    const int v    = 2 * warp + h;     // this half-warp's vertex
    const bool active = (v < V);

    // Coalesced idx load: lanes 0..31 cover 256B = idxs of both vertices.
    int2 pair = make_int2(0, 0);
    if (active) pair = idx2[v * (KNN / 2) + hl];

    // Block until convert's g_xh writes are visible.
    asm volatile("griddepcontrol.wait;" ::: "memory");

    if (!active) return;

    const __half2 zero = __float2half2_rn(0.0f);
    const __half2 ninf = __float2half2_rn(-65504.0f);
    __half2 sa0 = zero, sa1 = zero, sb0 = zero, sb1 = zero;  // 2x16 chains
    __half2 m0 = ninf, m1 = ninf;

    // Lane reads half2 pair (8B) at offset hl of each gathered row
    // (row = 32 half2 = 128B; 16 lanes * 8B cover it).
    const __half2* __restrict__ xl = g_xh + 2 * hl;
    const int srcbase = lane & 16;     // shuffles stay within the half-warp

    #pragma unroll
    for (int kk = 0; kk < KNN / 2; ++kk) {
        // k = 2*kk and k+1 live in the SAME source lane's int2.
        const int src  = srcbase + kk;
        const int idxE = __shfl_sync(0xffffffffu, pair.x, src);
        const int idxO = __shfl_sync(0xffffffffu, pair.y, src);
        const __half2* pE = xl + (size_t)(unsigned)idxE * (FDIM / 2);
        const __half2* pO = xl + (size_t)(unsigned)idxO * (FDIM / 2);

        // ---- both loads in ONE asm block: ptxas must keep MLP=2 ----
        unsigned int e0, e1, o0, o1;
        asm volatile(
            "ld.global.nc.v2.u32 {%0,%1}, [%4];\n\t"
            "ld.global.nc.v2.u32 {%2,%3}, [%5];\n\t"
            : "=r"(e0), "=r"(e1), "=r"(o0), "=r"(o1)
            : "l"(pE), "l"(pO));

        const __half2 ea = *(const __half2*)&e0;
        const __half2 eb = *(const __half2*)&e1;
        const __half2 oa = *(const __half2*)&o0;
        const __half2 ob = *(const __half2*)&o1;
        sa0 = __hadd2(sa0, ea);  sa1 = __hadd2(sa1, eb);
        sb0 = __hadd2(sb0, oa);  sb1 = __hadd2(sb1, ob);
        m0 = __hmax2(m0, ea);    m1 = __hmax2(m1, eb);
        m0 = __hmax2(m0, oa);    m1 = __hmax2(m1, ob);
    }

    const float2 f0a = __half22float2(sa0), f0b = __half22float2(sb0);
    const float2 f1a = __half22float2(sa1), f1b = __half22float2(sb1);
    const float2 fm0 = __half22float2(m0),  fm1 = __half22float2(m1);
    const float inv = 1.0f / KNN;

    // Lane holds features [4*hl, 4*hl+4) of vertex v.
    // out row = 128 floats = 32 float4: [mean 16 float4 | max 16 float4].
    float4 mean = make_float4((f0a.x + f0b.x) * inv, (f0a.y + f0b.y) * inv,
                              (f1a.x + f1b.x) * inv, (f1a.y + f1b.y) * inv);
    float4 mx   = make_float4(fm0.x, fm0.y, fm1.x, fm1.y);

    stg_cs_f4(&out4[v * 32 + hl],      mean);
    stg_cs_f4(&out4[v * 32 + 16 + hl], mx);
}

extern "C" void kernel_launch(void* const* d_in, const int* in_sizes, int n_in,
                              void* d_out, int out_size)
{
    const float4* x4   = (const float4*)d_in[0];  // x: [V, 64] float32
    const int2*   idx2 = (const int2*)d_in[1];    // idxs: [V, 32] int32
    float4*       out4 = (float4*)d_out;          // out: [V, 128] float32

    const int V  = in_sizes[0] / FDIM;            // 100000
    const int n8 = in_sizes[0] / 8;               // V*F/8 (16B per thread)

    convert_kernel<<<(n8 + 255) / 256, 256>>>(x4, n8);

    const int warps = (V + 1) / 2;                // 2 vertices per warp
    const int blocks = (warps + 7) / 8;           // 8 warps per block

    cudaLaunchConfig_t cfg = {};
    cfg.gridDim  = dim3((unsigned)blocks, 1, 1);
    cfg.blockDim = dim3(256, 1, 1);
    cfg.dynamicSmemBytes = 0;
    cfg.stream = 0;

    cudaLaunchAttribute attrs[1];
    attrs[0].id = cudaLaunchAttributeProgrammaticStreamSerialization;
    attrs[0].val.programmaticStreamSerializationAllowed = 1;
    cfg.attrs = attrs;
    cfg.numAttrs = 1;

    cudaLaunchKernelEx(&cfg, knn_mean_max_kernel, idx2, out4, V);
}